// round 2
// baseline (speedup 1.0000x reference)
#include <cuda_runtime.h>

// NCA step, packed-f32x2 version: each thread computes 2 horizontally-adjacent
// pixels using fma.rn.f32x2 (Blackwell packed fp32 path, 2x FFMA throughput).
// B=32, C=16, H=W=256, HID=128.

#define NB   32
#define NC   16
#define NH   256
#define NW   256
#define HID  128
#define HW   (NH * NW)

#define TLX  32        // tile width in pixels (16 threads x 2 px)
#define TLY  16        // tile height
#define TSX  (TLX + 2) // 34
#define TSY  (TLY + 2) // 18

// scratch: channel-3 plane of x_new
__device__ float g_ch3[NB * HW];

// smem layout (floats). u64 arrays first, all 16B-aligned.
#define SM_W1D  0                        // HID*48 pairs = 12288 floats
#define SM_W2D  (SM_W1D + HID * 48 * 2)  // HID*16 pairs = 4096 floats
#define SM_B1D  (SM_W2D + HID * 16 * 2)  // HID pairs    = 256 floats
#define SM_XS   (SM_B1D + HID * 2)       // NC*TSY*TSX   = 9792 floats
#define SM_FLOATS (SM_XS + NC * TSY * TSX)
#define SM_BYTES  (SM_FLOATS * 4)

typedef unsigned long long u64;

__device__ __forceinline__ u64 pk2(float lo, float hi) {
    u64 r; asm("mov.b64 %0, {%1,%2};" : "=l"(r) : "f"(lo), "f"(hi)); return r;
}
__device__ __forceinline__ void upk2(float& lo, float& hi, u64 v) {
    asm("mov.b64 {%0,%1}, %2;" : "=f"(lo), "=f"(hi) : "l"(v));
}
__device__ __forceinline__ u64 fma2(u64 a, u64 b, u64 c) {
    u64 d; asm("fma.rn.f32x2 %0, %1, %2, %3;" : "=l"(d) : "l"(a), "l"(b), "l"(c)); return d;
}
__device__ __forceinline__ u64 add2(u64 a, u64 b) {
    u64 d; asm("add.rn.f32x2 %0, %1, %2;" : "=l"(d) : "l"(a), "l"(b)); return d;
}

extern __shared__ float smem[];

__global__ __launch_bounds__(256)
void nca_main(const float* __restrict__ x, const float* __restrict__ ur,
              const float* __restrict__ w1, const float* __restrict__ b1,
              const float* __restrict__ w2, float* __restrict__ out) {
    const int b   = blockIdx.z;
    const int ty0 = blockIdx.y * TLY;
    const int tx0 = blockIdx.x * TLX;
    const int tid = threadIdx.y * 16 + threadIdx.x;  // 0..255

    // ---- stage duplicated weights ----
    {
        float2* w1d = (float2*)(smem + SM_W1D);
        for (int i = tid; i < HID * 48; i += 256) {
            float w = w1[i];
            w1d[i] = make_float2(w, w);
        }
        float2* w2d = (float2*)(smem + SM_W2D);
        for (int i = tid; i < HID * 16; i += 256) {
            int o = i >> 4, k = i & 15;
            float w = w2[k * HID + o];          // transposed: [o][k]
            w2d[i] = make_float2(w, w);
        }
        if (tid < HID) {
            float v = b1[tid];
            ((float2*)(smem + SM_B1D))[tid] = make_float2(v, v);
        }
    }

    // ---- stage input tile (+1 halo, zero-padded) ----
    {
        float* xs = smem + SM_XS;
        const float* xb = x + (size_t)b * NC * HW;
        for (int i = tid; i < NC * TSY * TSX; i += 256) {
            int c  = i / (TSY * TSX);
            int r  = i - c * (TSY * TSX);
            int yy = r / TSX, xx = r - (r / TSX) * TSX;
            int gy = ty0 + yy - 1, gx = tx0 + xx - 1;
            float v = 0.f;
            if (gy >= 0 && gy < NH && gx >= 0 && gx < NW)
                v = xb[c * HW + gy * NW + gx];
            xs[i] = v;
        }
    }
    __syncthreads();

    // ---- perception for the pixel pair, packed ----
    u64 yp[48];
    {
        const float* xs = smem + SM_XS;
        const int ly = threadIdx.y;
        const int lx = threadIdx.x;
        #pragma unroll
        for (int c = 0; c < NC; ++c) {
            const float* p = xs + c * (TSY * TSX) + ly * TSX + 2 * lx;
            float a00 = p[0],       a01 = p[1],           a02 = p[2],           a03 = p[3];
            float a10 = p[TSX],     a11 = p[TSX + 1],     a12 = p[TSX + 2],     a13 = p[TSX + 3];
            float a20 = p[2 * TSX], a21 = p[2 * TSX + 1], a22 = p[2 * TSX + 2], a23 = p[2 * TSX + 3];
            // identity
            yp[3 * c + 0] = pk2(a11, a12);
            // sobel x
            float sx0 = (a02 - a00 + 2.f * (a12 - a10) + a22 - a20) * 0.125f;
            float sx1 = (a03 - a01 + 2.f * (a13 - a11) + a23 - a21) * 0.125f;
            yp[3 * c + 1] = pk2(sx0, sx1);
            // sobel y
            float sy0 = (a20 - a00 + 2.f * (a21 - a01) + a22 - a02) * 0.125f;
            float sy1 = (a21 - a01 + 2.f * (a22 - a02) + a23 - a03) * 0.125f;
            yp[3 * c + 2] = pk2(sy0, sy1);
        }
    }

    // ---- MLP: h = relu(w1 @ y + b1); dx = w2 @ h  (all packed f32x2) ----
    u64 dxp[NC];
    #pragma unroll
    for (int k = 0; k < NC; ++k) dxp[k] = 0ULL;

    const ulonglong2* w1q = (const ulonglong2*)(smem + SM_W1D);  // [HID*24]
    const ulonglong2* w2q = (const ulonglong2*)(smem + SM_W2D);  // [HID*8]
    const u64*        b1d = (const u64*)(smem + SM_B1D);

    #pragma unroll 2
    for (int o = 0; o < HID; ++o) {
        const ulonglong2* wr = w1q + o * 24;
        u64 a0 = b1d[o], a1 = 0ULL, a2 = 0ULL, a3 = 0ULL;
        #pragma unroll
        for (int e = 0; e < 24; e += 2) {
            ulonglong2 wv0 = wr[e];
            ulonglong2 wv1 = wr[e + 1];
            a0 = fma2(yp[2 * e + 0], wv0.x, a0);
            a1 = fma2(yp[2 * e + 1], wv0.y, a1);
            a2 = fma2(yp[2 * e + 2], wv1.x, a2);
            a3 = fma2(yp[2 * e + 3], wv1.y, a3);
        }
        u64 hv = add2(add2(a0, a1), add2(a2, a3));
        float hl, hh;
        upk2(hl, hh, hv);
        hl = fmaxf(hl, 0.f);
        hh = fmaxf(hh, 0.f);
        u64 hp = pk2(hl, hh);

        const ulonglong2* w2r = w2q + o * 8;
        #pragma unroll
        for (int e = 0; e < 8; ++e) {
            ulonglong2 wv = w2r[e];
            dxp[2 * e + 0] = fma2(hp, wv.x, dxp[2 * e + 0]);
            dxp[2 * e + 1] = fma2(hp, wv.y, dxp[2 * e + 1]);
        }
    }

    // ---- stochastic update + store x_new (pixel pair as float2) ----
    const int gy  = ty0 + threadIdx.y;
    const int gx0 = tx0 + 2 * threadIdx.x;
    float2 urv = *(const float2*)(ur + (size_t)b * HW + gy * NW + gx0);
    u64 up = pk2(urv.x <= 0.5f ? 1.f : 0.f, urv.y <= 0.5f ? 1.f : 0.f);

    float* ob = out + (size_t)b * NC * HW + gy * NW + gx0;
    #pragma unroll
    for (int c = 0; c < NC; ++c) {
        u64 v = fma2(dxp[c], up, yp[3 * c]);   // x_center + dx*update
        float v0, v1;
        upk2(v0, v1, v);
        *(float2*)(ob + (size_t)c * HW) = make_float2(v0, v1);
        if (c == 3)
            *(float2*)(g_ch3 + (size_t)b * HW + gy * NW + gx0) = make_float2(v0, v1);
    }
}

__global__ void nca_mask(const float* __restrict__ x, float* __restrict__ out) {
    int idx = blockIdx.x * blockDim.x + threadIdx.x;  // over B*H*W
    if (idx >= NB * HW) return;
    int b = idx / HW;
    int r = idx - b * HW;
    int i = r / NW, j = r - (r / NW) * NW;

    const float* x3 = x + ((size_t)b * NC + 3) * HW;
    const float* n3 = g_ch3 + (size_t)b * HW;
    float m0 = -1e30f, m1 = -1e30f;
    #pragma unroll
    for (int dy = -1; dy <= 1; ++dy) {
        int yy = i + dy;
        if (yy < 0 || yy >= NH) continue;
        #pragma unroll
        for (int dxx = -1; dxx <= 1; ++dxx) {
            int xx = j + dxx;
            if (xx < 0 || xx >= NW) continue;
            m0 = fmaxf(m0, x3[yy * NW + xx]);
            m1 = fmaxf(m1, n3[yy * NW + xx]);
        }
    }
    bool alive = (m0 > 0.1f) && (m1 > 0.1f);
    if (!alive) {
        float* ob = out + (size_t)b * NC * HW + r;
        #pragma unroll
        for (int c = 0; c < NC; ++c) ob[c * HW] = 0.f;
    }
}

extern "C" void kernel_launch(void* const* d_in, const int* in_sizes, int n_in,
                              void* d_out, int out_size) {
    const float* x  = (const float*)d_in[0];
    const float* ur = (const float*)d_in[1];
    const float* w1 = (const float*)d_in[2];
    const float* b1 = (const float*)d_in[3];
    const float* w2 = (const float*)d_in[4];
    float* out = (float*)d_out;

    cudaFuncSetAttribute(nca_main, cudaFuncAttributeMaxDynamicSharedMemorySize, SM_BYTES);

    dim3 grid(NW / TLX, NH / TLY, NB);
    dim3 block(16, 16);
    nca_main<<<grid, block, SM_BYTES>>>(x, ur, w1, b1, w2, out);

    nca_mask<<<(NB * HW + 255) / 256, 256>>>(x, out);
}

// round 3
// speedup vs baseline: 2.9666x; 2.9666x over previous
#include <cuda_runtime.h>

// NCA step via tensor cores (mma.sync m16n8k8 tf32).
// L1: H[pix,128] = relu(Y^T[pix,48] @ W1^T + b1)   (A=Y row-major, B=W1 rows col-major)
// L2: DX[pix,16] = H[pix,128] @ W2^T
// Hidden dim is permuted (kappa) at weight-pack time so L1 D-fragments feed L2
// A-fragments directly in registers (no smem round-trip between layers).
// B=32, C=16, H=W=256, HID=128.

#define NB   32
#define NC   16
#define NH   256
#define NW   256
#define HID  128
#define HW   (NH * NW)

#define TLX  16   // CTA tile width (pixels)
#define TLY  8    // CTA tile height
#define NPIX (TLX * TLY)       // 128 pixels / CTA
#define HSX  (TLX + 2)         // 18
#define HSY  (TLY + 2)         // 10
#define YST  52                // Y smem row stride (floats), conflict-free

// ---- device scratch (no allocs) ----
__device__ float    g_ch3[NB * HW];
__device__ unsigned g_w1p[16 * 6 * 64];   // fragment-packed tf32 W1 (6144)
__device__ unsigned g_w2p[16 * 2 * 64];   // fragment-packed tf32 W2 (2048)

// smem layout (float words)
#define SM_W1  0                        // 6144 (tf32 bits)
#define SM_W2  (SM_W1 + 6144)           // 2048
#define SM_B1  (SM_W2 + 2048)           // 128 (fp32)
#define SM_UR  (SM_B1 + 128)            // 128
#define SM_XS  (SM_UR + 128)            // HSY*HSX*NC = 2880
#define SM_YS  (SM_XS + HSY * HSX * NC) // NPIX*YST = 6656
#define SM_FLOATS (SM_YS + NPIX * YST)
#define SM_BYTES  (SM_FLOATS * 4)

__device__ __forceinline__ unsigned f2tf(float x) {
    unsigned u; asm("cvt.rna.tf32.f32 %0, %1;" : "=r"(u) : "f"(x)); return u;
}

__device__ __forceinline__ void mma8(float c[4], const unsigned a[4],
                                     unsigned b0, unsigned b1) {
    asm volatile(
        "mma.sync.aligned.m16n8k8.row.col.f32.tf32.tf32.f32 "
        "{%0,%1,%2,%3}, {%4,%5,%6,%7}, {%8,%9}, {%0,%1,%2,%3};"
        : "+f"(c[0]), "+f"(c[1]), "+f"(c[2]), "+f"(c[3])
        : "r"(a[0]), "r"(a[1]), "r"(a[2]), "r"(a[3]), "r"(b0), "r"(b1));
}

// kappa: in-group hidden permutation so L1-D cols {2j,2j+1} == L2-A cols {j,j+4}
__device__ __forceinline__ int kappa(int s) { return (s >> 1) + 4 * (s & 1); }

// ---- prep: pack weights into fragment-ready tf32 layouts ----
__global__ void nca_prep(const float* __restrict__ w1, const float* __restrict__ w2) {
    int i = blockIdx.x * 256 + threadIdx.x;
    if (i < 6144) {
        int g = i / 384, rem = i % 384;
        int kg = rem / 64, e = rem % 64;
        int lane = e >> 1, half = e & 1;
        int h = 8 * g + kappa(lane >> 2);
        int f = 8 * kg + (lane & 3) + 4 * half;
        g_w1p[i] = f2tf(w1[h * 48 + f]);
    }
    int j = i - 6144;
    if (j >= 0 && j < 2048) {
        int g = j / 128, rem = j % 128;
        int ng = rem / 64, e = rem % 64;
        int lane = e >> 1, half = e & 1;
        int o  = (lane >> 2) + 8 * ng;
        int hh = 8 * g + (lane & 3) + 4 * half;
        g_w2p[j] = f2tf(w2[o * HID + hh]);
    }
}

extern __shared__ float smem[];

__global__ __launch_bounds__(128, 4)
void nca_main(const float* __restrict__ x, const float* __restrict__ ur,
              const float* __restrict__ b1, float* __restrict__ out) {
    const int b   = blockIdx.z;
    const int ty0 = blockIdx.y * TLY;
    const int tx0 = blockIdx.x * TLX;
    const int tid = threadIdx.x;

    unsigned* w1s = (unsigned*)(smem + SM_W1);
    unsigned* w2s = (unsigned*)(smem + SM_W2);
    float*    b1s = smem + SM_B1;
    float*    urs = smem + SM_UR;
    float*    xs  = smem + SM_XS;
    float*    ys  = smem + SM_YS;

    // ---- stage packed weights (coalesced uint4) ----
    {
        const uint4* s1 = (const uint4*)g_w1p;
        uint4*       d1 = (uint4*)w1s;
        #pragma unroll
        for (int i = tid; i < 6144 / 4; i += 128) d1[i] = s1[i];
        const uint4* s2 = (const uint4*)g_w2p;
        uint4*       d2s = (uint4*)w2s;
        #pragma unroll
        for (int i = tid; i < 2048 / 4; i += 128) d2s[i] = s2[i];
        if (tid < HID) b1s[tid] = b1[tid];
    }

    // ---- stage halo tile + update-rand ----
    {
        const float* xb = x + (size_t)b * NC * HW;
        for (int i = tid; i < NC * HSY * HSX; i += 128) {
            int c = i / (HSY * HSX);
            int rem = i - c * (HSY * HSX);
            int yy = rem / HSX, xx = rem - (rem / HSX) * HSX;
            int gy = ty0 + yy - 1, gx = tx0 + xx - 1;
            float v = 0.f;
            if (gy >= 0 && gy < NH && gx >= 0 && gx < NW)
                v = xb[c * HW + gy * NW + gx];
            xs[i] = v;
        }
        int py = tid / TLX, px = tid % TLX;   // tid < 128 == NPIX
        urs[tid] = ur[(size_t)b * HW + (ty0 + py) * NW + (tx0 + px)];
    }
    __syncthreads();

    // ---- perception: one pixel per thread -> Y[p][f], f = 3c+{id,sx,sy} ----
    {
        int py = tid / TLX, px = tid % TLX;
        float* yr = ys + tid * YST;
        #pragma unroll
        for (int c = 0; c < NC; ++c) {
            const float* p = xs + c * (HSY * HSX) + py * HSX + px;
            float a00 = p[0],        a01 = p[1],          a02 = p[2];
            float a10 = p[HSX],      a11 = p[HSX + 1],    a12 = p[HSX + 2];
            float a20 = p[2 * HSX],  a21 = p[2 * HSX + 1], a22 = p[2 * HSX + 2];
            yr[3 * c + 0] = a11;
            yr[3 * c + 1] = (a02 - a00 + 2.f * (a12 - a10) + a22 - a20) * 0.125f;
            yr[3 * c + 2] = (a20 - a00 + 2.f * (a21 - a01) + a22 - a02) * 0.125f;
        }
    }
    __syncthreads();

    // ---- MLP on tensor cores ----
    const int w    = tid >> 5;          // warp 0..3: rows 2w, 2w+1
    const int lane = tid & 31;
    const int qid  = lane >> 2;         // 0..7
    const int r4   = lane & 3;          // 0..3

    // A fragments for both M-tiles (tau = row within warp's pair)
    unsigned ya[2][6][4];
    #pragma unroll
    for (int t = 0; t < 2; ++t) {
        int p0 = (2 * w + t) * TLX + qid;
        const float* y0 = ys + p0 * YST;
        const float* y1 = ys + (p0 + 8) * YST;
        #pragma unroll
        for (int kg = 0; kg < 6; ++kg) {
            ya[t][kg][0] = f2tf(y0[8 * kg + r4]);
            ya[t][kg][1] = f2tf(y1[8 * kg + r4]);
            ya[t][kg][2] = f2tf(y0[8 * kg + r4 + 4]);
            ya[t][kg][3] = f2tf(y1[8 * kg + r4 + 4]);
        }
    }

    float d2[2][2][4];
    #pragma unroll
    for (int t = 0; t < 2; ++t)
        #pragma unroll
        for (int n = 0; n < 2; ++n)
            #pragma unroll
            for (int e = 0; e < 4; ++e) d2[t][n][e] = 0.f;

    #pragma unroll 1
    for (int g = 0; g < 16; ++g) {
        float bias0 = b1s[8 * g + r4];
        float bias1 = b1s[8 * g + r4 + 4];
        float c0[4] = {bias0, bias1, bias0, bias1};
        float c1[4] = {bias0, bias1, bias0, bias1};
        const uint2* w1g = (const uint2*)(w1s + g * 384) + lane;
        #pragma unroll
        for (int kg = 0; kg < 6; ++kg) {
            uint2 bb = w1g[kg * 32];
            mma8(c0, ya[0][kg], bb.x, bb.y);
            mma8(c1, ya[1][kg], bb.x, bb.y);
        }
        // relu + tf32 -> L2 A fragments (register permutation only)
        unsigned h0[4] = { f2tf(fmaxf(c0[0], 0.f)), f2tf(fmaxf(c0[2], 0.f)),
                           f2tf(fmaxf(c0[1], 0.f)), f2tf(fmaxf(c0[3], 0.f)) };
        unsigned h1[4] = { f2tf(fmaxf(c1[0], 0.f)), f2tf(fmaxf(c1[2], 0.f)),
                           f2tf(fmaxf(c1[1], 0.f)), f2tf(fmaxf(c1[3], 0.f)) };
        const uint2* w2g = (const uint2*)(w2s + g * 128) + lane;
        #pragma unroll
        for (int ng = 0; ng < 2; ++ng) {
            uint2 bb = w2g[ng * 32];
            mma8(d2[0][ng], h0, bb.x, bb.y);
            mma8(d2[1][ng], h1, bb.x, bb.y);
        }
    }

    // ---- epilogue: x + dx*update, store ----
    #pragma unroll
    for (int t = 0; t < 2; ++t) {
        int py = 2 * w + t;
        int gy = ty0 + py;
        int p0 = py * TLX + qid;
        int p1 = p0 + 8;
        float u0 = (urs[p0] <= 0.5f) ? 1.f : 0.f;
        float u1 = (urs[p1] <= 0.5f) ? 1.f : 0.f;
        int gx0 = tx0 + qid, gx1 = gx0 + 8;
        float* ob = out + (size_t)b * NC * HW + gy * NW;
        #pragma unroll
        for (int ng = 0; ng < 2; ++ng) {
            #pragma unroll
            for (int bq = 0; bq < 2; ++bq) {
                int ch = 8 * ng + 2 * r4 + bq;
                float v0 = fmaf(d2[t][ng][bq],     u0, ys[p0 * YST + 3 * ch]);
                float v1 = fmaf(d2[t][ng][bq + 2], u1, ys[p1 * YST + 3 * ch]);
                ob[(size_t)ch * HW + gx0] = v0;
                ob[(size_t)ch * HW + gx1] = v1;
                if (ch == 3) {
                    g_ch3[(size_t)b * HW + gy * NW + gx0] = v0;
                    g_ch3[(size_t)b * HW + gy * NW + gx1] = v1;
                }
            }
        }
    }
}

__global__ void nca_mask(const float* __restrict__ x, float* __restrict__ out) {
    int idx = blockIdx.x * blockDim.x + threadIdx.x;
    if (idx >= NB * HW) return;
    int b = idx / HW;
    int r = idx - b * HW;
    int i = r / NW, j = r - (r / NW) * NW;

    const float* x3 = x + ((size_t)b * NC + 3) * HW;
    const float* n3 = g_ch3 + (size_t)b * HW;
    float m0 = -1e30f, m1 = -1e30f;
    #pragma unroll
    for (int dy = -1; dy <= 1; ++dy) {
        int yy = i + dy;
        if (yy < 0 || yy >= NH) continue;
        #pragma unroll
        for (int dxx = -1; dxx <= 1; ++dxx) {
            int xx = j + dxx;
            if (xx < 0 || xx >= NW) continue;
            m0 = fmaxf(m0, x3[yy * NW + xx]);
            m1 = fmaxf(m1, n3[yy * NW + xx]);
        }
    }
    bool alive = (m0 > 0.1f) && (m1 > 0.1f);
    if (!alive) {
        float* ob = out + (size_t)b * NC * HW + r;
        #pragma unroll
        for (int c = 0; c < NC; ++c) ob[c * HW] = 0.f;
    }
}

extern "C" void kernel_launch(void* const* d_in, const int* in_sizes, int n_in,
                              void* d_out, int out_size) {
    const float* x  = (const float*)d_in[0];
    const float* ur = (const float*)d_in[1];
    const float* w1 = (const float*)d_in[2];
    const float* b1 = (const float*)d_in[3];
    const float* w2 = (const float*)d_in[4];
    float* out = (float*)d_out;

    cudaFuncSetAttribute(nca_main, cudaFuncAttributeMaxDynamicSharedMemorySize, SM_BYTES);

    nca_prep<<<32, 256>>>(w1, w2);

    dim3 grid(NW / TLX, NH / TLY, NB);
    nca_main<<<grid, 128, SM_BYTES>>>(x, ur, b1, out);

    nca_mask<<<(NB * HW + 255) / 256, 256>>>(x, out);
}

// round 4
// speedup vs baseline: 3.6868x; 1.2427x over previous
#include <cuda_runtime.h>

// NCA step via tensor cores (mma.sync m16n8k8 tf32), occupancy/ILP-tuned.
// 256 threads, 16x16-pixel CTA tile, 2 CTAs/SM. Y stored pre-converted to
// tf32; exact fp32 x-center for the epilogue comes from the xs halo tile.
// B=32, C=16, H=W=256, HID=128.

#define NB   32
#define NC   16
#define NH   256
#define NW   256
#define HID  128
#define HW   (NH * NW)

#define TLX  16
#define TLY  16
#define NPIX (TLX * TLY)   // 256
#define HSX  (TLX + 2)     // 18
#define HSY  (TLY + 2)     // 18
#define YST  52            // conflict-free row stride

__device__ float    g_ch3[NB * HW];
__device__ unsigned g_w1p[16 * 6 * 64];
__device__ unsigned g_w2p[16 * 2 * 64];

// smem layout (4B words)
#define SM_W1  0                          // 6144
#define SM_W2  (SM_W1 + 6144)             // 2048
#define SM_B1  (SM_W2 + 2048)             // 128
#define SM_UR  (SM_B1 + 128)              // 256
#define SM_XS  (SM_UR + 256)              // 16*18*18 = 5184
#define SM_YS  (SM_XS + HSY * HSX * NC)   // 256*52 = 13312
#define SM_WORDS (SM_YS + NPIX * YST)
#define SM_BYTES (SM_WORDS * 4)

__device__ __forceinline__ unsigned f2tf(float x) {
    unsigned u; asm("cvt.rna.tf32.f32 %0, %1;" : "=r"(u) : "f"(x)); return u;
}

__device__ __forceinline__ void mma8(float c[4], const unsigned a[4],
                                     unsigned b0, unsigned b1) {
    asm volatile(
        "mma.sync.aligned.m16n8k8.row.col.f32.tf32.tf32.f32 "
        "{%0,%1,%2,%3}, {%4,%5,%6,%7}, {%8,%9}, {%0,%1,%2,%3};"
        : "+f"(c[0]), "+f"(c[1]), "+f"(c[2]), "+f"(c[3])
        : "r"(a[0]), "r"(a[1]), "r"(a[2]), "r"(a[3]), "r"(b0), "r"(b1));
}

__device__ __forceinline__ int kappa(int s) { return (s >> 1) + 4 * (s & 1); }

__global__ void nca_prep(const float* __restrict__ w1, const float* __restrict__ w2) {
    int i = blockIdx.x * 256 + threadIdx.x;
    if (i < 6144) {
        int g = i / 384, rem = i % 384;
        int kg = rem / 64, e = rem % 64;
        int lane = e >> 1, half = e & 1;
        int h = 8 * g + kappa(lane >> 2);
        int f = 8 * kg + (lane & 3) + 4 * half;
        g_w1p[i] = f2tf(w1[h * 48 + f]);
    }
    int j = i - 6144;
    if (j >= 0 && j < 2048) {
        int g = j / 128, rem = j % 128;
        int ng = rem / 64, e = rem % 64;
        int lane = e >> 1, half = e & 1;
        int o  = (lane >> 2) + 8 * ng;
        int hh = 8 * g + (lane & 3) + 4 * half;
        g_w2p[j] = f2tf(w2[o * HID + hh]);
    }
}

extern __shared__ float smem[];

__global__ __launch_bounds__(256, 2)
void nca_main(const float* __restrict__ x, const float* __restrict__ ur,
              const float* __restrict__ b1, float* __restrict__ out) {
    const int b   = blockIdx.z;
    const int ty0 = blockIdx.y * TLY;
    const int tx0 = blockIdx.x * TLX;
    const int tid = threadIdx.x;

    unsigned* w1s = (unsigned*)(smem + SM_W1);
    unsigned* w2s = (unsigned*)(smem + SM_W2);
    float*    b1s = smem + SM_B1;
    float*    urs = smem + SM_UR;
    float*    xs  = smem + SM_XS;
    unsigned* ysu = (unsigned*)(smem + SM_YS);

    // ---- stage packed weights ----
    {
        const uint4* s1 = (const uint4*)g_w1p;
        uint4*       d1 = (uint4*)w1s;
        #pragma unroll
        for (int i = tid; i < 6144 / 4; i += 256) d1[i] = s1[i];
        const uint4* s2 = (const uint4*)g_w2p;
        uint4*       d2p = (uint4*)w2s;
        #pragma unroll
        for (int i = tid; i < 2048 / 4; i += 256) d2p[i] = s2[i];
        if (tid < HID) b1s[tid] = b1[tid];
    }

    // ---- stage halo tile + update-rand ----
    {
        const float* xb = x + (size_t)b * NC * HW;
        for (int i = tid; i < NC * HSY * HSX; i += 256) {
            int c = i / (HSY * HSX);
            int rem = i - c * (HSY * HSX);
            int yy = rem / HSX, xx = rem - (rem / HSX) * HSX;
            int gy = ty0 + yy - 1, gx = tx0 + xx - 1;
            float v = 0.f;
            if (gy >= 0 && gy < NH && gx >= 0 && gx < NW)
                v = xb[c * HW + gy * NW + gx];
            xs[i] = v;
        }
        int py = tid / TLX, px = tid % TLX;
        urs[tid] = ur[(size_t)b * HW + (ty0 + py) * NW + (tx0 + px)];
    }
    __syncthreads();

    // ---- perception -> tf32 Y rows ----
    {
        int py = tid / TLX, px = tid % TLX;
        unsigned* yr = ysu + tid * YST;
        #pragma unroll
        for (int c = 0; c < NC; ++c) {
            const float* p = xs + c * (HSY * HSX) + py * HSX + px;
            float a00 = p[0],        a01 = p[1],           a02 = p[2];
            float a10 = p[HSX],      a11 = p[HSX + 1],     a12 = p[HSX + 2];
            float a20 = p[2 * HSX],  a21 = p[2 * HSX + 1], a22 = p[2 * HSX + 2];
            yr[3 * c + 0] = f2tf(a11);
            yr[3 * c + 1] = f2tf((a02 - a00 + 2.f * (a12 - a10) + a22 - a20) * 0.125f);
            yr[3 * c + 2] = f2tf((a20 - a00 + 2.f * (a21 - a01) + a22 - a02) * 0.125f);
        }
    }
    __syncthreads();

    // ---- MLP on tensor cores ----
    const int w    = tid >> 5;       // 8 warps: pixel rows 2w, 2w+1
    const int lane = tid & 31;
    const int qid  = lane >> 2;
    const int r4   = lane & 3;

    unsigned ya[2][6][4];
    #pragma unroll
    for (int t = 0; t < 2; ++t) {
        int p0 = (2 * w + t) * TLX + qid;
        const unsigned* y0 = ysu + p0 * YST;
        const unsigned* y1 = ysu + (p0 + 8) * YST;
        #pragma unroll
        for (int kg = 0; kg < 6; ++kg) {
            ya[t][kg][0] = y0[8 * kg + r4];
            ya[t][kg][1] = y1[8 * kg + r4];
            ya[t][kg][2] = y0[8 * kg + r4 + 4];
            ya[t][kg][3] = y1[8 * kg + r4 + 4];
        }
    }

    float d2[2][2][4];
    #pragma unroll
    for (int t = 0; t < 2; ++t)
        #pragma unroll
        for (int n = 0; n < 2; ++n)
            #pragma unroll
            for (int e = 0; e < 4; ++e) d2[t][n][e] = 0.f;

    #pragma unroll 2
    for (int g = 0; g < 16; ++g) {
        float bias0 = b1s[8 * g + r4];
        float bias1 = b1s[8 * g + r4 + 4];
        float c0[4] = {bias0, bias1, bias0, bias1};
        float c1[4] = {bias0, bias1, bias0, bias1};
        const uint2* w1g = (const uint2*)(w1s + g * 384) + lane;
        #pragma unroll
        for (int kg = 0; kg < 6; ++kg) {
            uint2 bb = w1g[kg * 32];
            mma8(c0, ya[0][kg], bb.x, bb.y);
            mma8(c1, ya[1][kg], bb.x, bb.y);
        }
        unsigned h0[4] = { f2tf(fmaxf(c0[0], 0.f)), f2tf(fmaxf(c0[2], 0.f)),
                           f2tf(fmaxf(c0[1], 0.f)), f2tf(fmaxf(c0[3], 0.f)) };
        unsigned h1[4] = { f2tf(fmaxf(c1[0], 0.f)), f2tf(fmaxf(c1[2], 0.f)),
                           f2tf(fmaxf(c1[1], 0.f)), f2tf(fmaxf(c1[3], 0.f)) };
        const uint2* w2g = (const uint2*)(w2s + g * 128) + lane;
        #pragma unroll
        for (int ng = 0; ng < 2; ++ng) {
            uint2 bb = w2g[ng * 32];
            mma8(d2[0][ng], h0, bb.x, bb.y);
            mma8(d2[1][ng], h1, bb.x, bb.y);
        }
    }

    // ---- epilogue: x + dx*update (exact fp32 x from xs) ----
    #pragma unroll
    for (int t = 0; t < 2; ++t) {
        int py = 2 * w + t;
        int gy = ty0 + py;
        int p0 = py * TLX + qid;
        int p1 = p0 + 8;
        float u0 = (urs[p0] <= 0.5f) ? 1.f : 0.f;
        float u1 = (urs[p1] <= 0.5f) ? 1.f : 0.f;
        int gx0 = tx0 + qid, gx1 = gx0 + 8;
        float* ob = out + (size_t)b * NC * HW + gy * NW;
        #pragma unroll
        for (int ng = 0; ng < 2; ++ng) {
            #pragma unroll
            for (int bq = 0; bq < 2; ++bq) {
                int ch = 8 * ng + 2 * r4 + bq;
                const float* xc = xs + ch * (HSY * HSX) + (py + 1) * HSX + 1;
                float v0 = fmaf(d2[t][ng][bq],     u0, xc[qid]);
                float v1 = fmaf(d2[t][ng][bq + 2], u1, xc[qid + 8]);
                ob[(size_t)ch * HW + gx0] = v0;
                ob[(size_t)ch * HW + gx1] = v1;
                if (ch == 3) {
                    g_ch3[(size_t)b * HW + gy * NW + gx0] = v0;
                    g_ch3[(size_t)b * HW + gy * NW + gx1] = v1;
                }
            }
        }
    }
}

// mask: 4 pixels/thread, shared column maxes
__global__ void nca_mask(const float* __restrict__ x, float* __restrict__ out) {
    int idx = blockIdx.x * blockDim.x + threadIdx.x;   // over B*H*W/4
    if (idx >= NB * HW / 4) return;
    int b = idx / (HW / 4);
    int r = idx - b * (HW / 4);
    int i  = r / (NW / 4);
    int j0 = (r - i * (NW / 4)) * 4;

    const float* x3 = x + ((size_t)b * NC + 3) * HW;
    const float* n3 = g_ch3 + (size_t)b * HW;

    float cm0[6], cm1[6];
    #pragma unroll
    for (int k = 0; k < 6; ++k) {
        int jj = j0 - 1 + k;
        float a = -1e30f, c = -1e30f;
        if (jj >= 0 && jj < NW) {
            #pragma unroll
            for (int dy = -1; dy <= 1; ++dy) {
                int yy = i + dy;
                if (yy < 0 || yy >= NH) continue;
                a = fmaxf(a, x3[yy * NW + jj]);
                c = fmaxf(c, n3[yy * NW + jj]);
            }
        }
        cm0[k] = a; cm1[k] = c;
    }
    #pragma unroll
    for (int q = 0; q < 4; ++q) {
        float m0 = fmaxf(fmaxf(cm0[q], cm0[q + 1]), cm0[q + 2]);
        float m1 = fmaxf(fmaxf(cm1[q], cm1[q + 1]), cm1[q + 2]);
        if (!((m0 > 0.1f) && (m1 > 0.1f))) {
            float* ob = out + (size_t)b * NC * HW + i * NW + j0 + q;
            #pragma unroll
            for (int c = 0; c < NC; ++c) ob[(size_t)c * HW] = 0.f;
        }
    }
}

extern "C" void kernel_launch(void* const* d_in, const int* in_sizes, int n_in,
                              void* d_out, int out_size) {
    const float* x  = (const float*)d_in[0];
    const float* ur = (const float*)d_in[1];
    const float* w1 = (const float*)d_in[2];
    const float* b1 = (const float*)d_in[3];
    const float* w2 = (const float*)d_in[4];
    float* out = (float*)d_out;

    cudaFuncSetAttribute(nca_main, cudaFuncAttributeMaxDynamicSharedMemorySize, SM_BYTES);

    nca_prep<<<32, 256>>>(w1, w2);

    dim3 grid(NW / TLX, NH / TLY, NB);
    nca_main<<<grid, 256, SM_BYTES>>>(x, ur, b1, out);

    nca_mask<<<(NB * HW / 4 + 255) / 256, 256>>>(x, out);
}

// round 5
// speedup vs baseline: 5.3241x; 1.4441x over previous
#include <cuda_runtime.h>
#include <cuda_fp16.h>

// NCA step via tensor cores, fp16 m16n8k16 (f32 accumulate).
// fp16 mantissa == tf32 mantissa (10 bits); all values range-safe for fp16.
// kappa-permuted hidden dim chains L1 D-frags into L2 A-frags in registers.
// B=32, C=16, H=W=256, HID=128.

#define NB   32
#define NC   16
#define NH   256
#define NW   256
#define HID  128
#define HW   (NH * NW)

#define TLX  16
#define TLY  16
#define NPIX (TLX * TLY)
#define HSX  (TLX + 2)
#define HSY  (TLY + 2)
#define YSTW 28            // Y row stride in u32 words (24 data + pad, conflict-free)

__device__ float    g_ch3[NB * HW];
__device__ unsigned g_w1p[16 * 3 * 64];   // 3072 f16x2 words
__device__ unsigned g_w2p[8 * 2 * 64];    // 1024 f16x2 words

// smem layout (4B words)
#define SM_W1  0                          // 3072
#define SM_W2  (SM_W1 + 3072)             // 1024
#define SM_B1  (SM_W2 + 1024)             // 128
#define SM_UR  (SM_B1 + 128)              // 256
#define SM_XS  (SM_UR + 256)              // 5184
#define SM_YS  (SM_XS + HSY * HSX * NC)   // 256*28 = 7168
#define SM_WORDS (SM_YS + NPIX * YSTW)
#define SM_BYTES (SM_WORDS * 4)

__device__ __forceinline__ unsigned pk16(float lo, float hi) {
    __half2 h = __floats2half2_rn(lo, hi);
    return *(unsigned*)&h;
}

__device__ __forceinline__ void mma16(float c[4], const unsigned a[4],
                                      unsigned b0, unsigned b1) {
    asm volatile(
        "mma.sync.aligned.m16n8k16.row.col.f32.f16.f16.f32 "
        "{%0,%1,%2,%3}, {%4,%5,%6,%7}, {%8,%9}, {%0,%1,%2,%3};"
        : "+f"(c[0]), "+f"(c[1]), "+f"(c[2]), "+f"(c[3])
        : "r"(a[0]), "r"(a[1]), "r"(a[2]), "r"(a[3]), "r"(b0), "r"(b1));
}

// kappa: hidden in-group permutation (L1 D cols <-> L2 A k-slots)
__device__ __forceinline__ int kappa(int s) { return (s >> 1) + 4 * (s & 1); }

// ---- prep: fragment-ready f16x2 weight packing ----
__global__ void nca_prep(const float* __restrict__ w1, const float* __restrict__ w2) {
    int i = blockIdx.x * 256 + threadIdx.x;
    if (i < 3072) {
        // i = ((g*3 + kg2)*32 + lane)*2 + r
        int r = i & 1, lane = (i >> 1) & 31;
        int kg2 = (i >> 6) % 3, g = i / 192;
        int t4 = lane & 3, q = lane >> 2;
        int h  = 8 * g + kappa(q);
        int f0 = 16 * kg2 + 2 * t4 + 8 * r;
        g_w1p[i] = pk16(w1[h * 48 + f0], w1[h * 48 + f0 + 1]);
    }
    int j = i - 3072;
    if (j >= 0 && j < 1024) {
        // j = ((p*2 + ng)*32 + lane)*2 + r
        int r = j & 1, lane = (j >> 1) & 31;
        int ng = (j >> 6) & 1, p = j >> 7;
        int t4 = lane & 3, q = lane >> 2;
        int o  = q + 8 * ng;
        int h0 = 16 * p + 8 * r + t4;       // kappa(2t4)=t4, kappa(2t4+1)=t4+4
        g_w2p[j] = pk16(w2[o * HID + h0], w2[o * HID + h0 + 4]);
    }
}

extern __shared__ float smem[];

__global__ __launch_bounds__(256, 3)
void nca_main(const float* __restrict__ x, const float* __restrict__ ur,
              const float* __restrict__ b1, float* __restrict__ out) {
    const int b   = blockIdx.z;
    const int ty0 = blockIdx.y * TLY;
    const int tx0 = blockIdx.x * TLX;
    const int tid = threadIdx.x;

    unsigned* w1s = (unsigned*)(smem + SM_W1);
    unsigned* w2s = (unsigned*)(smem + SM_W2);
    float*    b1s = smem + SM_B1;
    float*    urs = smem + SM_UR;
    float*    xs  = smem + SM_XS;
    unsigned* ysw = (unsigned*)(smem + SM_YS);

    // ---- stage packed weights ----
    {
        const uint4* s1 = (const uint4*)g_w1p;
        uint4*       d1 = (uint4*)w1s;
        #pragma unroll
        for (int i = tid; i < 3072 / 4; i += 256) d1[i] = s1[i];
        const uint4* s2 = (const uint4*)g_w2p;
        uint4*       d2p = (uint4*)w2s;
        if (tid < 1024 / 4) d2p[tid] = s2[tid];
        if (tid < HID) b1s[tid] = b1[tid];
    }

    // ---- stage halo tile + update-rand ----
    {
        const float* xb = x + (size_t)b * NC * HW;
        for (int i = tid; i < NC * HSY * HSX; i += 256) {
            int c = i / (HSY * HSX);
            int rem = i - c * (HSY * HSX);
            int yy = rem / HSX, xx = rem - (rem / HSX) * HSX;
            int gy = ty0 + yy - 1, gx = tx0 + xx - 1;
            float v = 0.f;
            if (gy >= 0 && gy < NH && gx >= 0 && gx < NW)
                v = xb[c * HW + gy * NW + gx];
            xs[i] = v;
        }
        int py = tid / TLX, px = tid % TLX;
        urs[tid] = ur[(size_t)b * HW + (ty0 + py) * NW + (tx0 + px)];
    }
    __syncthreads();

    // ---- perception -> f16x2 Y rows (48 halves = 24 words) ----
    {
        int py = tid / TLX, px = tid % TLX;
        unsigned* yr = ysw + tid * YSTW;
        float pend = 0.f;
        #pragma unroll
        for (int c = 0; c < NC; ++c) {
            const float* p = xs + c * (HSY * HSX) + py * HSX + px;
            float a00 = p[0],        a01 = p[1],           a02 = p[2];
            float a10 = p[HSX],      a11 = p[HSX + 1],     a12 = p[HSX + 2];
            float a20 = p[2 * HSX],  a21 = p[2 * HSX + 1], a22 = p[2 * HSX + 2];
            float sx = (a02 - a00 + 2.f * (a12 - a10) + a22 - a20) * 0.125f;
            float sy = (a20 - a00 + 2.f * (a21 - a01) + a22 - a02) * 0.125f;
            if ((c & 1) == 0) {
                yr[(3 * c) / 2] = pk16(a11, sx);
                pend = sy;
            } else {
                yr[(3 * c - 1) / 2] = pk16(pend, a11);
                yr[(3 * c + 1) / 2] = pk16(sx, sy);
            }
        }
    }
    __syncthreads();

    // ---- MLP on tensor cores ----
    const int w    = tid >> 5;
    const int lane = tid & 31;
    const int qid  = lane >> 2;
    const int r4   = lane & 3;

    // A fragments: [tile][kg2][4]
    unsigned ya[2][3][4];
    #pragma unroll
    for (int t = 0; t < 2; ++t) {
        int p0 = (2 * w + t) * TLX + qid;
        const unsigned* y0 = ysw + p0 * YSTW;
        const unsigned* y1 = ysw + (p0 + 8) * YSTW;
        #pragma unroll
        for (int kg = 0; kg < 3; ++kg) {
            ya[t][kg][0] = y0[8 * kg + r4];
            ya[t][kg][1] = y1[8 * kg + r4];
            ya[t][kg][2] = y0[8 * kg + r4 + 4];
            ya[t][kg][3] = y1[8 * kg + r4 + 4];
        }
    }

    float d2[2][2][4];
    #pragma unroll
    for (int t = 0; t < 2; ++t)
        #pragma unroll
        for (int n = 0; n < 2; ++n)
            #pragma unroll
            for (int e = 0; e < 4; ++e) d2[t][n][e] = 0.f;

    #pragma unroll 2
    for (int p = 0; p < 8; ++p) {
        // L1 for groups g0=2p, g1=2p+1
        float c0[2][4], c1[2][4];   // [gg][frag], per tile via two arrays
        #pragma unroll
        for (int gg = 0; gg < 2; ++gg) {
            int g = 2 * p + gg;
            float bias0 = b1s[8 * g + r4];
            float bias1 = b1s[8 * g + r4 + 4];
            c0[gg][0] = bias0; c0[gg][1] = bias1; c0[gg][2] = bias0; c0[gg][3] = bias1;
            c1[gg][0] = bias0; c1[gg][1] = bias1; c1[gg][2] = bias0; c1[gg][3] = bias1;
            const uint2* w1g = (const uint2*)w1s + (g * 3) * 32 + lane;
            #pragma unroll
            for (int kg = 0; kg < 3; ++kg) {
                uint2 bb = w1g[kg * 32];
                mma16(c0[gg], ya[0][kg], bb.x, bb.y);
                mma16(c1[gg], ya[1][kg], bb.x, bb.y);
            }
        }
        // relu + pack -> L2 A fragments (k16 spans both groups)
        unsigned h0[4] = {
            pk16(fmaxf(c0[0][0], 0.f), fmaxf(c0[0][1], 0.f)),
            pk16(fmaxf(c0[0][2], 0.f), fmaxf(c0[0][3], 0.f)),
            pk16(fmaxf(c0[1][0], 0.f), fmaxf(c0[1][1], 0.f)),
            pk16(fmaxf(c0[1][2], 0.f), fmaxf(c0[1][3], 0.f)) };
        unsigned h1[4] = {
            pk16(fmaxf(c1[0][0], 0.f), fmaxf(c1[0][1], 0.f)),
            pk16(fmaxf(c1[0][2], 0.f), fmaxf(c1[0][3], 0.f)),
            pk16(fmaxf(c1[1][0], 0.f), fmaxf(c1[1][1], 0.f)),
            pk16(fmaxf(c1[1][2], 0.f), fmaxf(c1[1][3], 0.f)) };
        const uint2* w2g = (const uint2*)w2s + (p * 2) * 32 + lane;
        #pragma unroll
        for (int ng = 0; ng < 2; ++ng) {
            uint2 bb = w2g[ng * 32];
            mma16(d2[0][ng], h0, bb.x, bb.y);
            mma16(d2[1][ng], h1, bb.x, bb.y);
        }
    }

    // ---- epilogue: x + dx*update (exact fp32 x from xs) ----
    #pragma unroll
    for (int t = 0; t < 2; ++t) {
        int py = 2 * w + t;
        int gy = ty0 + py;
        int p0 = py * TLX + qid;
        int p1 = p0 + 8;
        float u0 = (urs[p0] <= 0.5f) ? 1.f : 0.f;
        float u1 = (urs[p1] <= 0.5f) ? 1.f : 0.f;
        int gx0 = tx0 + qid, gx1 = gx0 + 8;
        float* ob = out + (size_t)b * NC * HW + gy * NW;
        #pragma unroll
        for (int ng = 0; ng < 2; ++ng) {
            #pragma unroll
            for (int bq = 0; bq < 2; ++bq) {
                int ch = 8 * ng + 2 * r4 + bq;
                const float* xc = xs + ch * (HSY * HSX) + (py + 1) * HSX + 1;
                float v0 = fmaf(d2[t][ng][bq],     u0, xc[qid]);
                float v1 = fmaf(d2[t][ng][bq + 2], u1, xc[qid + 8]);
                ob[(size_t)ch * HW + gx0] = v0;
                ob[(size_t)ch * HW + gx1] = v1;
                if (ch == 3) {
                    g_ch3[(size_t)b * HW + gy * NW + gx0] = v0;
                    g_ch3[(size_t)b * HW + gy * NW + gx1] = v1;
                }
            }
        }
    }
}

// mask: 4 pixels/thread, shared column maxes
__global__ void nca_mask(const float* __restrict__ x, float* __restrict__ out) {
    int idx = blockIdx.x * blockDim.x + threadIdx.x;
    if (idx >= NB * HW / 4) return;
    int b = idx / (HW / 4);
    int r = idx - b * (HW / 4);
    int i  = r / (NW / 4);
    int j0 = (r - i * (NW / 4)) * 4;

    const float* x3 = x + ((size_t)b * NC + 3) * HW;
    const float* n3 = g_ch3 + (size_t)b * HW;

    float cm0[6], cm1[6];
    #pragma unroll
    for (int k = 0; k < 6; ++k) {
        int jj = j0 - 1 + k;
        float a = -1e30f, c = -1e30f;
        if (jj >= 0 && jj < NW) {
            #pragma unroll
            for (int dy = -1; dy <= 1; ++dy) {
                int yy = i + dy;
                if (yy < 0 || yy >= NH) continue;
                a = fmaxf(a, x3[yy * NW + jj]);
                c = fmaxf(c, n3[yy * NW + jj]);
            }
        }
        cm0[k] = a; cm1[k] = c;
    }
    #pragma unroll
    for (int q = 0; q < 4; ++q) {
        float m0 = fmaxf(fmaxf(cm0[q], cm0[q + 1]), cm0[q + 2]);
        float m1 = fmaxf(fmaxf(cm1[q], cm1[q + 1]), cm1[q + 2]);
        if (!((m0 > 0.1f) && (m1 > 0.1f))) {
            float* ob = out + (size_t)b * NC * HW + i * NW + j0 + q;
            #pragma unroll
            for (int c = 0; c < NC; ++c) ob[(size_t)c * HW] = 0.f;
        }
    }
}

extern "C" void kernel_launch(void* const* d_in, const int* in_sizes, int n_in,
                              void* d_out, int out_size) {
    const float* x  = (const float*)d_in[0];
    const float* ur = (const float*)d_in[1];
    const float* w1 = (const float*)d_in[2];
    const float* b1 = (const float*)d_in[3];
    const float* w2 = (const float*)d_in[4];
    float* out = (float*)d_out;

    cudaFuncSetAttribute(nca_main, cudaFuncAttributeMaxDynamicSharedMemorySize, SM_BYTES);

    nca_prep<<<16, 256>>>(w1, w2);

    dim3 grid(NW / TLX, NH / TLY, NB);
    nca_main<<<grid, 256, SM_BYTES>>>(x, ur, b1, out);

    nca_mask<<<(NB * HW / 4 + 255) / 256, 256>>>(x, out);
}